// round 1
// baseline (speedup 1.0000x reference)
#include <cuda_runtime.h>

// Problem constants
static constexpr int LEN   = 2048;   // sequence length
static constexpr int WIDTH = 1536;   // qkv width
static constexpr int BQ    = 64;     // query tile
static constexpr int BK    = 64;     // key tile
static constexpr int NKT   = LEN / BK;   // 32 k-tiles
static constexpr int PST   = 68;     // padded stride for P tile [s][t]

// Shared memory layout (floats):
// Qs[64][64] (c-major), Ks[64][64], Vs[64][64], Ps[64][68], m[64], l[64], f[64]
static constexpr int SMEM_FLOATS = 3 * 4096 + 64 * PST + 3 * 64;  // 16832
static constexpr int SMEM_BYTES  = SMEM_FLOATS * 4;               // 67328

__global__ void __launch_bounds__(256, 3)
attn_fwd_kernel(const float* __restrict__ qkv, float* __restrict__ out)
{
    extern __shared__ float sm[];
    float* Qs   = sm;                    // [c][t]
    float* Ks   = Qs + 4096;             // [c][s]
    float* Vs   = Ks + 4096;             // [c][s]
    float* Ps   = Vs + 4096;             // [s][t], stride PST
    float* mrow = Ps + 64 * PST;         // running max per t
    float* lrow = mrow + 64;             // running sum per t
    float* frow = lrow + 64;             // rescale factor per t (this tile)

    const int tid   = threadIdx.x;
    const int qt    = blockIdx.x;        // query tile index (0..31)
    const int bh    = blockIdx.y;        // head-batch index (0..63)
    const int batch = bh >> 3;
    const int h     = bh & 7;

    const float* base  = qkv + (size_t)batch * (WIDTH * LEN) + (size_t)(h * 192) * LEN;
    const float* qbase = base;               // channels 0..63
    const float* kbase = base + 64 * LEN;    // channels 64..127
    const float* vbase = base + 128 * LEN;   // channels 128..191

    // ---- Load Q tile (pre-scaled by 1/sqrt(d) = 0.125 = scale^2 folded into Q) ----
    #pragma unroll
    for (int r = 0; r < 4; r++) {
        int idx = tid + r * 256;         // 0..1023 float4 slots
        int c   = idx >> 4;              // 16 float4 per row of 64
        int t4  = idx & 15;
        float4 v = *reinterpret_cast<const float4*>(qbase + c * LEN + qt * BQ + t4 * 4);
        v.x *= 0.125f; v.y *= 0.125f; v.z *= 0.125f; v.w *= 0.125f;
        *reinterpret_cast<float4*>(Qs + c * 64 + t4 * 4) = v;
    }
    if (tid < 64) { mrow[tid] = -3.0e38f; lrow[tid] = 0.0f; }

    const int trow = tid >> 4;   // 0..15
    const int tcol = tid & 15;   // 0..15

    // Output accumulator, map B: o[i][j] = O[c = 4*trow+i][t = 4*tcol+j]
    float o[4][4];
    #pragma unroll
    for (int i = 0; i < 4; i++)
        #pragma unroll
        for (int j = 0; j < 4; j++) o[i][j] = 0.0f;

    for (int kt = 0; kt < NKT; kt++) {
        __syncthreads();   // previous PV done reading Vs/Ps; stats settled

        // ---- Load K and V tiles ----
        #pragma unroll
        for (int r = 0; r < 4; r++) {
            int idx = tid + r * 256;
            int c   = idx >> 4;
            int s4  = idx & 15;
            *reinterpret_cast<float4*>(Ks + c * 64 + s4 * 4) =
                *reinterpret_cast<const float4*>(kbase + c * LEN + kt * BK + s4 * 4);
        }
        #pragma unroll
        for (int r = 0; r < 4; r++) {
            int idx = tid + r * 256;
            int c   = idx >> 4;
            int s4  = idx & 15;
            *reinterpret_cast<float4*>(Vs + c * 64 + s4 * 4) =
                *reinterpret_cast<const float4*>(vbase + c * LEN + kt * BK + s4 * 4);
        }
        __syncthreads();

        // ---- S = Q^T K, map A: acc[i][j] = S[t = 4*trow+i][s = 4*tcol+j] ----
        float acc[4][4];
        #pragma unroll
        for (int i = 0; i < 4; i++)
            #pragma unroll
            for (int j = 0; j < 4; j++) acc[i][j] = 0.0f;

        #pragma unroll 8
        for (int c = 0; c < 64; c++) {
            float4 qv = *reinterpret_cast<const float4*>(Qs + c * 64 + 4 * trow);
            float4 kv = *reinterpret_cast<const float4*>(Ks + c * 64 + 4 * tcol);
            float qa[4] = {qv.x, qv.y, qv.z, qv.w};
            float ka[4] = {kv.x, kv.y, kv.z, kv.w};
            #pragma unroll
            for (int i = 0; i < 4; i++)
                #pragma unroll
                for (int j = 0; j < 4; j++)
                    acc[i][j] = fmaf(qa[i], ka[j], acc[i][j]);
        }

        // ---- Online softmax over this tile (row = t, spread across 16 tcol lanes) ----
        float mnew[4], fct[4], rs[4];
        #pragma unroll
        for (int i = 0; i < 4; i++) {
            float mx = fmaxf(fmaxf(acc[i][0], acc[i][1]), fmaxf(acc[i][2], acc[i][3]));
            #pragma unroll
            for (int d = 8; d > 0; d >>= 1)
                mx = fmaxf(mx, __shfl_xor_sync(0xffffffffu, mx, d));
            float mo = mrow[4 * trow + i];
            float mn = fmaxf(mo, mx);
            float f  = __expf(mo - mn);
            float sum = 0.0f;
            #pragma unroll
            for (int j = 0; j < 4; j++) {
                float e = __expf(acc[i][j] - mn);
                acc[i][j] = e;
                sum += e;
            }
            #pragma unroll
            for (int d = 8; d > 0; d >>= 1)
                sum += __shfl_xor_sync(0xffffffffu, sum, d);
            mnew[i] = mn; fct[i] = f; rs[i] = sum;
        }
        if (tcol == 0) {
            #pragma unroll
            for (int i = 0; i < 4; i++) {
                int t = 4 * trow + i;
                lrow[t] = lrow[t] * fct[i] + rs[i];
                mrow[t] = mnew[i];
                frow[t] = fct[i];
            }
        }

        // ---- Store P transposed: Ps[s][t] ----
        #pragma unroll
        for (int j = 0; j < 4; j++) {
            float4 pv = make_float4(acc[0][j], acc[1][j], acc[2][j], acc[3][j]);
            *reinterpret_cast<float4*>(Ps + (4 * tcol + j) * PST + 4 * trow) = pv;
        }
        __syncthreads();

        // ---- O rescale + PV gemm, map B: c = 4*trow+i, t = 4*tcol+j ----
        float4 fv = *reinterpret_cast<const float4*>(frow + 4 * tcol);
        float fj[4] = {fv.x, fv.y, fv.z, fv.w};
        #pragma unroll
        for (int i = 0; i < 4; i++)
            #pragma unroll
            for (int j = 0; j < 4; j++) o[i][j] *= fj[j];

        #pragma unroll 8
        for (int s = 0; s < 64; s++) {
            float4 pp = *reinterpret_cast<const float4*>(Ps + s * PST + 4 * tcol);
            float pa[4] = {pp.x, pp.y, pp.z, pp.w};
            float va[4];
            #pragma unroll
            for (int i = 0; i < 4; i++)
                va[i] = Vs[(4 * trow + i) * 64 + s];
            #pragma unroll
            for (int i = 0; i < 4; i++)
                #pragma unroll
                for (int j = 0; j < 4; j++)
                    o[i][j] = fmaf(va[i], pa[j], o[i][j]);
        }
    }

    // ---- Epilogue: divide by l, write out[c][t] coalesced ----
    float4 lv = *reinterpret_cast<const float4*>(lrow + 4 * tcol);
    float inv[4] = {1.0f / lv.x, 1.0f / lv.y, 1.0f / lv.z, 1.0f / lv.w};

    float* obase = out + (size_t)batch * (512 * LEN) + (size_t)(h * 64) * LEN + qt * BQ;
    #pragma unroll
    for (int i = 0; i < 4; i++) {
        int c = 4 * trow + i;
        float4 w = make_float4(o[i][0] * inv[0], o[i][1] * inv[1],
                               o[i][2] * inv[2], o[i][3] * inv[3]);
        *reinterpret_cast<float4*>(obase + (size_t)c * LEN + 4 * tcol) = w;
    }
}

extern "C" void kernel_launch(void* const* d_in, const int* in_sizes, int n_in,
                              void* d_out, int out_size)
{
    const float* qkv = (const float*)d_in[0];
    float* out = (float*)d_out;

    cudaFuncSetAttribute(attn_fwd_kernel,
                         cudaFuncAttributeMaxDynamicSharedMemorySize, SMEM_BYTES);

    dim3 grid(LEN / BQ, 64);   // 32 q-tiles x 64 head-batches
    attn_fwd_kernel<<<grid, 256, SMEM_BYTES>>>(qkv, out);
}

// round 3
// speedup vs baseline: 3.3832x; 3.3832x over previous
#include <cuda_runtime.h>
#include <cuda_fp16.h>
#include <cstdint>

#define DINL __device__ __forceinline__

static constexpr int LEN = 2048;
static constexpr int NKT = 32;          // key tiles of 64

// ---- smem layout in 32-bit words ----
// per KV buffer: KHI[32 c2][68] | KLO[32][68] | VHI[64 c][36]
static constexpr int KHI_W = 0;
static constexpr int KLO_W = 2176;
static constexpr int VHI_W = 4352;
static constexpr int BUF_W = 6656;                 // words per buffer
static constexpr int SMEM_W = 2 * BUF_W;           // 13312 words
static constexpr int SMEM_BYTES = SMEM_W * 4;      // 53248 (Q stage 8448w / O stage 8320w overlap)

// ---------- helpers ----------
DINL uint32_t pack2(float x, float y) {
    __half2 h = __floats2half2_rn(x, y);
    return *reinterpret_cast<uint32_t*>(&h);
}
DINL void split2(float x, float y, uint32_t& hi, uint32_t& lo) {
    __half2 h = __floats2half2_rn(x, y);
    hi = *reinterpret_cast<uint32_t*>(&h);
    float2 hf = __half22float2(h);
    __half2 l = __floats2half2_rn(x - hf.x, y - hf.y);
    lo = *reinterpret_cast<uint32_t*>(&l);
}
DINL void mma16816(float* c, const uint32_t* a, uint32_t b0, uint32_t b1) {
    asm volatile(
        "mma.sync.aligned.m16n8k16.row.col.f32.f16.f16.f32 "
        "{%0,%1,%2,%3}, {%4,%5,%6,%7}, {%8,%9}, {%0,%1,%2,%3};"
        : "+f"(c[0]), "+f"(c[1]), "+f"(c[2]), "+f"(c[3])
        : "r"(a[0]), "r"(a[1]), "r"(a[2]), "r"(a[3]), "r"(b0), "r"(b1));
}

// gmem -> registers for next K/V tile
DINL void load_kv_regs(const float* kb, const float* vb, int kt, int tid,
                       float4 (&kr)[4], float4 (&vr)[4]) {
    #pragma unroll
    for (int i = 0; i < 2; i++) {
        int slot = tid + 256 * i;
        int c2 = slot >> 4, s4 = slot & 15;
        const float* p = kb + (size_t)(2 * c2) * LEN + kt * 64 + 4 * s4;
        kr[2*i]     = *reinterpret_cast<const float4*>(p);
        kr[2*i + 1] = *reinterpret_cast<const float4*>(p + LEN);
    }
    #pragma unroll
    for (int i = 0; i < 4; i++) {
        int slot = tid + 256 * i;
        int c = slot >> 4, s4 = slot & 15;
        vr[i] = *reinterpret_cast<const float4*>(vb + (size_t)c * LEN + kt * 64 + 4 * s4);
    }
}

// registers -> packed half2 smem tiles
DINL void store_kv_smem(uint32_t* smw, int bufw, int tid,
                        const float4 (&kr)[4], const float4 (&vr)[4]) {
    #pragma unroll
    for (int i = 0; i < 2; i++) {
        int slot = tid + 256 * i;
        int c2 = slot >> 4, s4 = slot & 15;
        const float* A = reinterpret_cast<const float*>(&kr[2*i]);
        const float* B = reinterpret_cast<const float*>(&kr[2*i + 1]);
        uint32_t hw[4], lw[4];
        #pragma unroll
        for (int w = 0; w < 4; w++) split2(A[w], B[w], hw[w], lw[w]);
        int base = c2 * 68 + 4 * s4;
        *reinterpret_cast<uint4*>(smw + bufw + KHI_W + base) = make_uint4(hw[0], hw[1], hw[2], hw[3]);
        *reinterpret_cast<uint4*>(smw + bufw + KLO_W + base) = make_uint4(lw[0], lw[1], lw[2], lw[3]);
    }
    #pragma unroll
    for (int i = 0; i < 4; i++) {
        int slot = tid + 256 * i;
        int c = slot >> 4, s4 = slot & 15;
        const float* V = reinterpret_cast<const float*>(&vr[i]);
        int base = bufw + VHI_W + c * 36 + 2 * s4;
        *reinterpret_cast<uint2*>(smw + base) = make_uint2(pack2(V[0], V[1]), pack2(V[2], V[3]));
    }
}

__global__ void __launch_bounds__(256)
attn_hmma_kernel(const float* __restrict__ qkv, float* __restrict__ out)
{
    extern __shared__ float sm[];
    uint32_t* smw = reinterpret_cast<uint32_t*>(sm);

    const int tid  = threadIdx.x;
    const int warp = tid >> 5, lane = tid & 31;
    const int g    = lane >> 2, tig = lane & 3;

    const int qt = blockIdx.x;          // 0..15
    const int bh = blockIdx.y;          // 0..63
    const int batch = bh >> 3, h = bh & 7;
    const float* base = qkv + (size_t)batch * (1536 * LEN) + (size_t)(h * 192) * LEN;
    const float* qb = base;
    const float* kb = base + 64 * LEN;
    const float* vb = base + 128 * LEN;

    // ---- stage Q (fp32, [c][t] stride 132) ----
    #pragma unroll
    for (int i = 0; i < 8; i++) {
        int slot = tid + 256 * i;
        int c = slot >> 5, t4 = slot & 31;
        float4 v = *reinterpret_cast<const float4*>(qb + (size_t)c * LEN + qt * 128 + 4 * t4);
        v.x *= 0.125f; v.y *= 0.125f; v.z *= 0.125f; v.w *= 0.125f;
        *reinterpret_cast<float4*>(sm + c * 132 + 4 * t4) = v;
    }
    // overlap: kick off first K/V tile loads
    float4 kr[4], vr[4];
    load_kv_regs(kb, vb, 0, tid, kr, vr);
    __syncthreads();

    // ---- build Q A-fragments (hi/lo split) ----
    uint32_t qhi[4][4], qlo[4][4];
    const int t0 = warp * 16 + g;
    #pragma unroll
    for (int kk = 0; kk < 4; kk++) {
        int c0 = 16 * kk + 2 * tig;
        float x0 = sm[(c0    ) * 132 + t0    ], x1 = sm[(c0 + 1) * 132 + t0    ];
        float x2 = sm[(c0    ) * 132 + t0 + 8], x3 = sm[(c0 + 1) * 132 + t0 + 8];
        float x4 = sm[(c0 + 8) * 132 + t0    ], x5 = sm[(c0 + 9) * 132 + t0    ];
        float x6 = sm[(c0 + 8) * 132 + t0 + 8], x7 = sm[(c0 + 9) * 132 + t0 + 8];
        split2(x0, x1, qhi[kk][0], qlo[kk][0]);
        split2(x2, x3, qhi[kk][1], qlo[kk][1]);
        split2(x4, x5, qhi[kk][2], qlo[kk][2]);
        split2(x6, x7, qhi[kk][3], qlo[kk][3]);
    }
    __syncthreads();   // Q stage consumed; buffers may be overwritten now

    store_kv_smem(smw, 0, tid, kr, vr);
    load_kv_regs(kb, vb, 1, tid, kr, vr);
    __syncthreads();

    float m0 = -1e30f, m1 = -1e30f, l0 = 0.0f, l1 = 0.0f;
    float o[8][4];
    #pragma unroll
    for (int j = 0; j < 8; j++)
        #pragma unroll
        for (int r = 0; r < 4; r++) o[j][r] = 0.0f;

    for (int kt = 0; kt < NKT; kt++) {
        const int bufw = (kt & 1) * BUF_W;

        // ---- QK: S[t][s], 3-chain fp16 split ----
        float s[8][4];
        #pragma unroll
        for (int j = 0; j < 8; j++)
            #pragma unroll
            for (int r = 0; r < 4; r++) s[j][r] = 0.0f;

        #pragma unroll
        for (int j = 0; j < 8; j++) {
            uint32_t bh0[4], bh1[4], bl0[4], bl1[4];
            const int col = g + 8 * j;
            #pragma unroll
            for (int kk = 0; kk < 4; kk++) {
                int r = 8 * kk + tig;
                bh0[kk] = smw[bufw + KHI_W + (r    ) * 68 + col];
                bh1[kk] = smw[bufw + KHI_W + (r + 4) * 68 + col];
                bl0[kk] = smw[bufw + KLO_W + (r    ) * 68 + col];
                bl1[kk] = smw[bufw + KLO_W + (r + 4) * 68 + col];
            }
            #pragma unroll
            for (int kk = 0; kk < 4; kk++) mma16816(s[j], qhi[kk], bh0[kk], bh1[kk]);
            #pragma unroll
            for (int kk = 0; kk < 4; kk++) mma16816(s[j], qhi[kk], bl0[kk], bl1[kk]);
            #pragma unroll
            for (int kk = 0; kk < 4; kk++) mma16816(s[j], qlo[kk], bh0[kk], bh1[kk]);
        }

        // ---- online softmax (rows g and g+8, spread over 4 tig lanes) ----
        float mx0 = m0, mx1 = m1;
        #pragma unroll
        for (int j = 0; j < 8; j++) {
            mx0 = fmaxf(mx0, fmaxf(s[j][0], s[j][1]));
            mx1 = fmaxf(mx1, fmaxf(s[j][2], s[j][3]));
        }
        mx0 = fmaxf(mx0, __shfl_xor_sync(0xffffffffu, mx0, 1));
        mx0 = fmaxf(mx0, __shfl_xor_sync(0xffffffffu, mx0, 2));
        mx1 = fmaxf(mx1, __shfl_xor_sync(0xffffffffu, mx1, 1));
        mx1 = fmaxf(mx1, __shfl_xor_sync(0xffffffffu, mx1, 2));
        const float f0 = __expf(m0 - mx0), f1 = __expf(m1 - mx1);
        m0 = mx0; m1 = mx1;
        float sum0 = 0.0f, sum1 = 0.0f;
        #pragma unroll
        for (int j = 0; j < 8; j++) {
            s[j][0] = __expf(s[j][0] - m0); sum0 += s[j][0];
            s[j][1] = __expf(s[j][1] - m0); sum0 += s[j][1];
            s[j][2] = __expf(s[j][2] - m1); sum1 += s[j][2];
            s[j][3] = __expf(s[j][3] - m1); sum1 += s[j][3];
        }
        sum0 += __shfl_xor_sync(0xffffffffu, sum0, 1);
        sum0 += __shfl_xor_sync(0xffffffffu, sum0, 2);
        sum1 += __shfl_xor_sync(0xffffffffu, sum1, 1);
        sum1 += __shfl_xor_sync(0xffffffffu, sum1, 2);
        l0 = l0 * f0 + sum0;
        l1 = l1 * f1 + sum1;

        // ---- P A-fragments (register pass-through) ----
        uint32_t ap[4][4];
        #pragma unroll
        for (int kk = 0; kk < 4; kk++) {
            ap[kk][0] = pack2(s[2*kk][0],     s[2*kk][1]);
            ap[kk][1] = pack2(s[2*kk][2],     s[2*kk][3]);
            ap[kk][2] = pack2(s[2*kk + 1][0], s[2*kk + 1][1]);
            ap[kk][3] = pack2(s[2*kk + 1][2], s[2*kk + 1][3]);
        }

        // ---- PV: rescale O, accumulate ----
        #pragma unroll
        for (int jc = 0; jc < 8; jc++) {
            o[jc][0] *= f0; o[jc][1] *= f0; o[jc][2] *= f1; o[jc][3] *= f1;
            const int vbase = bufw + VHI_W + (8 * jc + g) * 36;
            #pragma unroll
            for (int kk = 0; kk < 4; kk++) {
                uint32_t b0 = smw[vbase + tig + 8 * kk];
                uint32_t b1 = smw[vbase + tig + 8 * kk + 4];
                mma16816(o[jc], ap[kk], b0, b1);
            }
        }

        __syncthreads();
        if (kt + 1 < NKT) store_kv_smem(smw, (~kt & 1) * BUF_W, tid, kr, vr);
        if (kt + 2 < NKT) load_kv_regs(kb, vb, kt + 2, tid, kr, vr);
        __syncthreads();
    }

    // ---- epilogue: stage O in smem [t][c] stride 65, then coalesced store ----
    const float inv0 = 1.0f / l0, inv1 = 1.0f / l1;
    #pragma unroll
    for (int jc = 0; jc < 8; jc++) {
        int c = 8 * jc + 2 * tig;
        sm[(t0    ) * 65 + c    ] = o[jc][0] * inv0;
        sm[(t0    ) * 65 + c + 1] = o[jc][1] * inv0;
        sm[(t0 + 8) * 65 + c    ] = o[jc][2] * inv1;
        sm[(t0 + 8) * 65 + c + 1] = o[jc][3] * inv1;
    }
    __syncthreads();

    float* ob = out + (size_t)batch * (512 * LEN) + (size_t)(h * 64) * LEN + qt * 128;
    #pragma unroll
    for (int i = 0; i < 8; i++) {
        int slot = tid + 256 * i;
        int c = slot >> 5, t4 = slot & 31;
        float4 w = make_float4(sm[(4*t4    ) * 65 + c], sm[(4*t4 + 1) * 65 + c],
                               sm[(4*t4 + 2) * 65 + c], sm[(4*t4 + 3) * 65 + c]);
        *reinterpret_cast<float4*>(ob + (size_t)c * LEN + 4 * t4) = w;
    }
}

extern "C" void kernel_launch(void* const* d_in, const int* in_sizes, int n_in,
                              void* d_out, int out_size)
{
    const float* qkv = (const float*)d_in[0];
    float* out = (float*)d_out;

    cudaFuncSetAttribute(attn_hmma_kernel,
                         cudaFuncAttributeMaxDynamicSharedMemorySize, SMEM_BYTES);

    dim3 grid(LEN / 128, 64);
    attn_hmma_kernel<<<grid, 256, SMEM_BYTES>>>(qkv, out);
}

// round 4
// speedup vs baseline: 3.5704x; 1.0553x over previous
#include <cuda_runtime.h>
#include <cuda_fp16.h>
#include <cstdint>

#define DINL __device__ __forceinline__

static constexpr int LEN = 2048;
static constexpr int NKT = 32;

// ---- smem layout (bytes) ----
static constexpr int OFF_KHI = 0;        // [64 c][72 s] halves, row stride 144B
static constexpr int OFF_KLO = 9216;
static constexpr int OFF_VHI = 18432;    // [64 c][72 s] halves
static constexpr int OFF_STG = 27648;    // fp32 stage: 2 bufs x (K 16KB + V 16KB)
static constexpr int STG_BUF = 32768;
static constexpr int SMEM_BYTES = OFF_STG + 2 * STG_BUF;   // 93184 -> 2 CTAs/SM

// ---------- helpers ----------
DINL uint32_t smem_u32(const void* p) {
    uint32_t a;
    asm("{ .reg .u64 t; cvta.to.shared.u64 t, %1; cvt.u32.u64 %0, t; }" : "=r"(a) : "l"(p));
    return a;
}
DINL uint32_t pack2(float x, float y) {
    __half2 h = __floats2half2_rn(x, y);
    return *reinterpret_cast<uint32_t*>(&h);
}
DINL void split2(float x, float y, uint32_t& hi, uint32_t& lo) {
    __half2 h = __floats2half2_rn(x, y);
    hi = *reinterpret_cast<uint32_t*>(&h);
    float2 hf = __half22float2(h);
    __half2 l = __floats2half2_rn(x - hf.x, y - hf.y);
    lo = *reinterpret_cast<uint32_t*>(&l);
}
DINL void mma16816(float* c, const uint32_t* a, uint32_t b0, uint32_t b1) {
    asm volatile(
        "mma.sync.aligned.m16n8k16.row.col.f32.f16.f16.f32 "
        "{%0,%1,%2,%3}, {%4,%5,%6,%7}, {%8,%9}, {%0,%1,%2,%3};"
        : "+f"(c[0]), "+f"(c[1]), "+f"(c[2]), "+f"(c[3])
        : "r"(a[0]), "r"(a[1]), "r"(a[2]), "r"(a[3]), "r"(b0), "r"(b1));
}
DINL void ldmx4(uint32_t* r, uint32_t a) {
    asm volatile("ldmatrix.sync.aligned.m8n8.x4.shared.b16 {%0,%1,%2,%3}, [%4];"
                 : "=r"(r[0]), "=r"(r[1]), "=r"(r[2]), "=r"(r[3]) : "r"(a));
}
DINL void ldmx4t(uint32_t* r, uint32_t a) {
    asm volatile("ldmatrix.sync.aligned.m8n8.x4.trans.shared.b16 {%0,%1,%2,%3}, [%4];"
                 : "=r"(r[0]), "=r"(r[1]), "=r"(r[2]), "=r"(r[3]) : "r"(a));
}
DINL void cp16(uint32_t dst, const float* src) {
    asm volatile("cp.async.cg.shared.global [%0], [%1], 16;" :: "r"(dst), "l"(src) : "memory");
}
DINL void cp_commit() { asm volatile("cp.async.commit_group;" ::: "memory"); }
template <int N> DINL void cp_wait() {
    asm volatile("cp.async.wait_group %0;" :: "n"(N) : "memory");
}

// issue cp.async for K/V tile kt into stage buffer `buf` (per-thread chunks)
DINL void stage_kv(uint32_t sb, const float* kb, const float* vb, int kt, int buf, int tid) {
    const uint32_t dst = sb + OFF_STG + buf * STG_BUF;
    const float* ks = kb + kt * 64;
    const float* vs = vb + kt * 64;
    #pragma unroll
    for (int i = 0; i < 8; i++) {
        int slot = tid + 128 * i;
        int c = slot >> 4, s4 = slot & 15;
        uint32_t o = (uint32_t)(c * 256 + s4 * 16);
        cp16(dst + o,         ks + (size_t)c * LEN + s4 * 4);
        cp16(dst + 16384 + o, vs + (size_t)c * LEN + s4 * 4);
    }
    cp_commit();
}

// fp32 stage -> half hi/lo tiles (each thread converts exactly the chunks it staged)
DINL void convert_kv(char* smc, int buf, int tid) {
    #pragma unroll
    for (int i = 0; i < 8; i++) {
        int slot = tid + 128 * i;
        int c = slot >> 4, s4 = slot & 15;
        const char* stg = smc + OFF_STG + buf * STG_BUF + c * 256 + s4 * 16;
        float4 kx = *reinterpret_cast<const float4*>(stg);
        uint32_t h0, l0, h1, l1;
        split2(kx.x, kx.y, h0, l0);
        split2(kx.z, kx.w, h1, l1);
        int ho = c * 144 + s4 * 8;
        *reinterpret_cast<uint2*>(smc + OFF_KHI + ho) = make_uint2(h0, h1);
        *reinterpret_cast<uint2*>(smc + OFF_KLO + ho) = make_uint2(l0, l1);
        float4 vx = *reinterpret_cast<const float4*>(stg + 16384);
        *reinterpret_cast<uint2*>(smc + OFF_VHI + ho) =
            make_uint2(pack2(vx.x, vx.y), pack2(vx.z, vx.w));
    }
}

__global__ void __launch_bounds__(128, 2)
attn_hmma2_kernel(const float* __restrict__ qkv, float* __restrict__ out)
{
    extern __shared__ char smc[];
    const uint32_t sb = smem_u32(smc);

    const int tid  = threadIdx.x;
    const int warp = tid >> 5, lane = tid & 31;
    const int g = lane >> 2, tig = lane & 3;

    const int qt = blockIdx.x;           // 0..15
    const int bh = blockIdx.y;           // 0..63
    const int batch = bh >> 3, h = bh & 7;
    const float* base = qkv + (size_t)batch * (1536 * LEN) + (size_t)(h * 192) * LEN;
    const float* qb = base;
    const float* kb = base + 64 * LEN;
    const float* vb = base + 128 * LEN;

    // kick off staging of first two K/V tiles
    stage_kv(sb, kb, vb, 0, 0, tid);
    stage_kv(sb, kb, vb, 1, 1, tid);

    // ---- Q A-fragments straight from gmem (one time), rows t = warp*32 + blk*16 + {g, g+8} ----
    uint32_t qhi[2][4][4], qlo[2][4][4];
    {
        const float* qp = qb + qt * 128;
        #pragma unroll
        for (int blk = 0; blk < 2; blk++) {
            int ta = warp * 32 + blk * 16 + g;
            #pragma unroll
            for (int kk = 0; kk < 4; kk++) {
                const float* q0 = qp + (size_t)(16 * kk + 2 * tig) * LEN;
                float x0 = q0[ta] * 0.125f,            x1 = q0[LEN + ta] * 0.125f;
                float x2 = q0[ta + 8] * 0.125f,        x3 = q0[LEN + ta + 8] * 0.125f;
                float x4 = q0[8 * LEN + ta] * 0.125f,  x5 = q0[9 * LEN + ta] * 0.125f;
                float x6 = q0[8 * LEN + ta + 8] * 0.125f, x7 = q0[9 * LEN + ta + 8] * 0.125f;
                split2(x0, x1, qhi[blk][kk][0], qlo[blk][kk][0]);
                split2(x2, x3, qhi[blk][kk][1], qlo[blk][kk][1]);
                split2(x4, x5, qhi[blk][kk][2], qlo[blk][kk][2]);
                split2(x6, x7, qhi[blk][kk][3], qlo[blk][kk][3]);
            }
        }
    }

    float m[4], l[4];
    #pragma unroll
    for (int r = 0; r < 4; r++) { m[r] = -1e30f; l[r] = 0.0f; }
    float o[2][8][4];
    #pragma unroll
    for (int blk = 0; blk < 2; blk++)
        #pragma unroll
        for (int jc = 0; jc < 8; jc++)
            #pragma unroll
            for (int r = 0; r < 4; r++) o[blk][jc][r] = 0.0f;

    // first tile: wait stage(0), convert
    cp_wait<1>();
    __syncthreads();
    convert_kv(smc, 0, tid);
    __syncthreads();

    for (int kt = 0; kt < NKT; kt++) {
        // ---- QK: S[t][s], 3-chain fp16 split, B-frags via ldmatrix.trans ----
        float s[2][8][4];
        #pragma unroll
        for (int blk = 0; blk < 2; blk++)
            #pragma unroll
            for (int j = 0; j < 8; j++)
                #pragma unroll
                for (int r = 0; r < 4; r++) s[blk][j][r] = 0.0f;

        #pragma unroll
        for (int j = 0; j < 8; j++) {
            uint32_t bhf[8], blf[8];
            uint32_t a0 = sb + OFF_KHI + lane * 144 + j * 16;
            ldmx4t(bhf,     a0);
            ldmx4t(bhf + 4, a0 + 32 * 144);
            uint32_t a1 = a0 + (OFF_KLO - OFF_KHI);
            ldmx4t(blf,     a1);
            ldmx4t(blf + 4, a1 + 32 * 144);
            #pragma unroll
            for (int blk = 0; blk < 2; blk++)
                #pragma unroll
                for (int kk = 0; kk < 4; kk++) {
                    mma16816(s[blk][j], qhi[blk][kk], bhf[2 * kk], bhf[2 * kk + 1]);
                    mma16816(s[blk][j], qhi[blk][kk], blf[2 * kk], blf[2 * kk + 1]);
                    mma16816(s[blk][j], qlo[blk][kk], bhf[2 * kk], bhf[2 * kk + 1]);
                }
        }

        // ---- online softmax: 4 rows per thread (blk x {g, g+8}) ----
        float f[4];
        #pragma unroll
        for (int blk = 0; blk < 2; blk++) {
            float mx0 = m[2 * blk], mx1 = m[2 * blk + 1];
            #pragma unroll
            for (int j = 0; j < 8; j++) {
                mx0 = fmaxf(mx0, fmaxf(s[blk][j][0], s[blk][j][1]));
                mx1 = fmaxf(mx1, fmaxf(s[blk][j][2], s[blk][j][3]));
            }
            mx0 = fmaxf(mx0, __shfl_xor_sync(0xffffffffu, mx0, 1));
            mx0 = fmaxf(mx0, __shfl_xor_sync(0xffffffffu, mx0, 2));
            mx1 = fmaxf(mx1, __shfl_xor_sync(0xffffffffu, mx1, 1));
            mx1 = fmaxf(mx1, __shfl_xor_sync(0xffffffffu, mx1, 2));
            f[2 * blk]     = __expf(m[2 * blk] - mx0);
            f[2 * blk + 1] = __expf(m[2 * blk + 1] - mx1);
            m[2 * blk] = mx0; m[2 * blk + 1] = mx1;
            float s0 = 0.0f, s1 = 0.0f;
            #pragma unroll
            for (int j = 0; j < 8; j++) {
                s[blk][j][0] = __expf(s[blk][j][0] - mx0); s0 += s[blk][j][0];
                s[blk][j][1] = __expf(s[blk][j][1] - mx0); s0 += s[blk][j][1];
                s[blk][j][2] = __expf(s[blk][j][2] - mx1); s1 += s[blk][j][2];
                s[blk][j][3] = __expf(s[blk][j][3] - mx1); s1 += s[blk][j][3];
            }
            s0 += __shfl_xor_sync(0xffffffffu, s0, 1);
            s0 += __shfl_xor_sync(0xffffffffu, s0, 2);
            s1 += __shfl_xor_sync(0xffffffffu, s1, 1);
            s1 += __shfl_xor_sync(0xffffffffu, s1, 2);
            l[2 * blk]     = l[2 * blk]     * f[2 * blk]     + s0;
            l[2 * blk + 1] = l[2 * blk + 1] * f[2 * blk + 1] + s1;
        }

        // ---- P A-fragments (register pass-through) ----
        uint32_t ap[2][4][4];
        #pragma unroll
        for (int blk = 0; blk < 2; blk++)
            #pragma unroll
            for (int kk = 0; kk < 4; kk++) {
                ap[blk][kk][0] = pack2(s[blk][2 * kk][0],     s[blk][2 * kk][1]);
                ap[blk][kk][1] = pack2(s[blk][2 * kk][2],     s[blk][2 * kk][3]);
                ap[blk][kk][2] = pack2(s[blk][2 * kk + 1][0], s[blk][2 * kk + 1][1]);
                ap[blk][kk][3] = pack2(s[blk][2 * kk + 1][2], s[blk][2 * kk + 1][3]);
            }

        // ---- PV: rescale O, accumulate; V-frags via ldmatrix ----
        #pragma unroll
        for (int jc = 0; jc < 8; jc++) {
            uint32_t vf[8];
            uint32_t va = sb + OFF_VHI + (8 * jc + (lane & 7)) * 144 + (lane >> 3) * 16;
            ldmx4(vf,     va);
            ldmx4(vf + 4, va + 64);
            #pragma unroll
            for (int blk = 0; blk < 2; blk++) {
                o[blk][jc][0] *= f[2 * blk];
                o[blk][jc][1] *= f[2 * blk];
                o[blk][jc][2] *= f[2 * blk + 1];
                o[blk][jc][3] *= f[2 * blk + 1];
                #pragma unroll
                for (int kk = 0; kk < 4; kk++)
                    mma16816(o[blk][jc], ap[blk][kk], vf[2 * kk], vf[2 * kk + 1]);
            }
        }

        // ---- pipeline: stage kt+2, convert kt+1 ----
        if (kt + 2 < NKT) stage_kv(sb, kb, vb, kt + 2, kt & 1, tid);
        __syncthreads();                       // all warps done reading half tiles
        if (kt + 1 < NKT) {
            if (kt + 2 < NKT) cp_wait<1>(); else cp_wait<0>();
            convert_kv(smc, (kt + 1) & 1, tid);
            __syncthreads();
        }
    }

    // ---- epilogue: direct scalar stores (8 lanes fill each 32B sector) ----
    float inv[4];
    #pragma unroll
    for (int r = 0; r < 4; r++) inv[r] = 1.0f / l[r];

    float* ob = out + (size_t)batch * (512 * LEN) + (size_t)(h * 64) * LEN + qt * 128;
    #pragma unroll
    for (int blk = 0; blk < 2; blk++) {
        int ta = warp * 32 + blk * 16 + g;
        #pragma unroll
        for (int jc = 0; jc < 8; jc++) {
            int c = 8 * jc + 2 * tig;
            ob[(size_t)c * LEN + ta]           = o[blk][jc][0] * inv[2 * blk];
            ob[(size_t)(c + 1) * LEN + ta]     = o[blk][jc][1] * inv[2 * blk];
            ob[(size_t)c * LEN + ta + 8]       = o[blk][jc][2] * inv[2 * blk + 1];
            ob[(size_t)(c + 1) * LEN + ta + 8] = o[blk][jc][3] * inv[2 * blk + 1];
        }
    }
}

extern "C" void kernel_launch(void* const* d_in, const int* in_sizes, int n_in,
                              void* d_out, int out_size)
{
    const float* qkv = (const float*)d_in[0];
    float* out = (float*)d_out;

    cudaFuncSetAttribute(attn_hmma2_kernel,
                         cudaFuncAttributeMaxDynamicSharedMemorySize, SMEM_BYTES);

    dim3 grid(LEN / 128, 64);
    attn_hmma2_kernel<<<grid, 128, SMEM_BYTES>>>(qkv, out);
}

// round 5
// speedup vs baseline: 4.9287x; 1.3804x over previous
#include <cuda_runtime.h>
#include <cuda_fp16.h>
#include <cstdint>

#define DINL __device__ __forceinline__

static constexpr int LEN = 2048;
static constexpr int NKT = 32;

// ---- smem layout (bytes) ----
static constexpr int OFF_KHI = 0;        // [64 c][72 s] halves, row stride 144B
static constexpr int OFF_VHI = 9216;     // [64 c][72 s] halves
static constexpr int OFF_STG = 18432;    // fp32 stage: 2 bufs x (K 16KB + V 16KB)
static constexpr int STG_BUF = 32768;
static constexpr int SMEM_BYTES = OFF_STG + 2 * STG_BUF;   // 83968

// ---------- helpers ----------
DINL uint32_t smem_u32(const void* p) {
    uint32_t a;
    asm("{ .reg .u64 t; cvta.to.shared.u64 t, %1; cvt.u32.u64 %0, t; }" : "=r"(a) : "l"(p));
    return a;
}
DINL uint32_t pack2(float x, float y) {
    __half2 h = __floats2half2_rn(x, y);
    return *reinterpret_cast<uint32_t*>(&h);
}
DINL void split2(float x, float y, uint32_t& hi, uint32_t& lo) {
    __half2 h = __floats2half2_rn(x, y);
    hi = *reinterpret_cast<uint32_t*>(&h);
    float2 hf = __half22float2(h);
    __half2 l = __floats2half2_rn(x - hf.x, y - hf.y);
    lo = *reinterpret_cast<uint32_t*>(&l);
}
DINL void mma16816(float* c, const uint32_t* a, uint32_t b0, uint32_t b1) {
    asm volatile(
        "mma.sync.aligned.m16n8k16.row.col.f32.f16.f16.f32 "
        "{%0,%1,%2,%3}, {%4,%5,%6,%7}, {%8,%9}, {%0,%1,%2,%3};"
        : "+f"(c[0]), "+f"(c[1]), "+f"(c[2]), "+f"(c[3])
        : "r"(a[0]), "r"(a[1]), "r"(a[2]), "r"(a[3]), "r"(b0), "r"(b1));
}
DINL void ldmx4(uint32_t* r, uint32_t a) {
    asm volatile("ldmatrix.sync.aligned.m8n8.x4.shared.b16 {%0,%1,%2,%3}, [%4];"
                 : "=r"(r[0]), "=r"(r[1]), "=r"(r[2]), "=r"(r[3]) : "r"(a));
}
DINL void ldmx4t(uint32_t* r, uint32_t a) {
    asm volatile("ldmatrix.sync.aligned.m8n8.x4.trans.shared.b16 {%0,%1,%2,%3}, [%4];"
                 : "=r"(r[0]), "=r"(r[1]), "=r"(r[2]), "=r"(r[3]) : "r"(a));
}
DINL void cp16(uint32_t dst, const float* src) {
    asm volatile("cp.async.cg.shared.global [%0], [%1], 16;" :: "r"(dst), "l"(src) : "memory");
}
DINL void cp_commit() { asm volatile("cp.async.commit_group;" ::: "memory"); }
template <int N> DINL void cp_wait() {
    asm volatile("cp.async.wait_group %0;" :: "n"(N) : "memory");
}

// issue cp.async for K/V tile kt into stage buffer `buf` (256 threads, 4 chunks each)
DINL void stage_kv(uint32_t sb, const float* kb, const float* vb, int kt, int buf, int tid) {
    const uint32_t dst = sb + OFF_STG + buf * STG_BUF;
    const float* ks = kb + kt * 64;
    const float* vs = vb + kt * 64;
    #pragma unroll
    for (int i = 0; i < 4; i++) {
        int slot = tid + 256 * i;
        int c = slot >> 4, s4 = slot & 15;
        uint32_t o = (uint32_t)(c * 256 + s4 * 16);
        cp16(dst + o,         ks + (size_t)c * LEN + s4 * 4);
        cp16(dst + 16384 + o, vs + (size_t)c * LEN + s4 * 4);
    }
    cp_commit();
}

// fp32 stage -> half tiles (K rounded single-precision-hi only, V rounded)
DINL void convert_kv(char* smc, int buf, int tid) {
    #pragma unroll
    for (int i = 0; i < 4; i++) {
        int slot = tid + 256 * i;
        int c = slot >> 4, s4 = slot & 15;
        const char* stg = smc + OFF_STG + buf * STG_BUF + c * 256 + s4 * 16;
        float4 kx = *reinterpret_cast<const float4*>(stg);
        int ho = c * 144 + s4 * 8;
        *reinterpret_cast<uint2*>(smc + OFF_KHI + ho) =
            make_uint2(pack2(kx.x, kx.y), pack2(kx.z, kx.w));
        float4 vx = *reinterpret_cast<const float4*>(stg + 16384);
        *reinterpret_cast<uint2*>(smc + OFF_VHI + ho) =
            make_uint2(pack2(vx.x, vx.y), pack2(vx.z, vx.w));
    }
}

__global__ void __launch_bounds__(256, 1)
attn_hmma3_kernel(const float* __restrict__ qkv, float* __restrict__ out)
{
    extern __shared__ char smc[];
    const uint32_t sb = smem_u32(smc);

    const int tid  = threadIdx.x;
    const int warp = tid >> 5, lane = tid & 31;
    const int g = lane >> 2, tig = lane & 3;

    const int qt = blockIdx.x;           // 0..7 (256-query tiles)
    const int bh = blockIdx.y;           // 0..63
    const int batch = bh >> 3, h = bh & 7;
    const float* base = qkv + (size_t)batch * (1536 * LEN) + (size_t)(h * 192) * LEN;
    const float* qb = base;
    const float* kb = base + 64 * LEN;
    const float* vb = base + 128 * LEN;

    // kick off staging of first two K/V tiles
    stage_kv(sb, kb, vb, 0, 0, tid);
    stage_kv(sb, kb, vb, 1, 1, tid);

    // ---- Q A-fragments from gmem (hi/lo split), rows ta = warp*32 + blk*16 + {g, g+8} ----
    uint32_t qhi[2][4][4], qlo[2][4][4];
    {
        const float* qp = qb + qt * 256;
        #pragma unroll
        for (int blk = 0; blk < 2; blk++) {
            int ta = warp * 32 + blk * 16 + g;
            #pragma unroll
            for (int kk = 0; kk < 4; kk++) {
                const float* q0 = qp + (size_t)(16 * kk + 2 * tig) * LEN;
                float x0 = q0[ta] * 0.125f,               x1 = q0[LEN + ta] * 0.125f;
                float x2 = q0[ta + 8] * 0.125f,           x3 = q0[LEN + ta + 8] * 0.125f;
                float x4 = q0[8 * LEN + ta] * 0.125f,     x5 = q0[9 * LEN + ta] * 0.125f;
                float x6 = q0[8 * LEN + ta + 8] * 0.125f, x7 = q0[9 * LEN + ta + 8] * 0.125f;
                split2(x0, x1, qhi[blk][kk][0], qlo[blk][kk][0]);
                split2(x2, x3, qhi[blk][kk][1], qlo[blk][kk][1]);
                split2(x4, x5, qhi[blk][kk][2], qlo[blk][kk][2]);
                split2(x6, x7, qhi[blk][kk][3], qlo[blk][kk][3]);
            }
        }
    }

    float m[4], l[4];
    #pragma unroll
    for (int r = 0; r < 4; r++) { m[r] = -1e30f; l[r] = 0.0f; }
    float o[2][8][4];
    #pragma unroll
    for (int blk = 0; blk < 2; blk++)
        #pragma unroll
        for (int jc = 0; jc < 8; jc++)
            #pragma unroll
            for (int r = 0; r < 4; r++) o[blk][jc][r] = 0.0f;

    // first tile: wait stage(0), convert
    cp_wait<1>();
    __syncthreads();
    convert_kv(smc, 0, tid);
    __syncthreads();

    for (int kt = 0; kt < NKT; kt++) {
        // ---- QK: S[t][s] = (qhi + qlo) . khi  (2-chain) ----
        float s[2][8][4];
        #pragma unroll
        for (int blk = 0; blk < 2; blk++)
            #pragma unroll
            for (int j = 0; j < 8; j++)
                #pragma unroll
                for (int r = 0; r < 4; r++) s[blk][j][r] = 0.0f;

        #pragma unroll
        for (int j = 0; j < 8; j++) {
            uint32_t bhf[8];
            uint32_t a0 = sb + OFF_KHI + lane * 144 + j * 16;
            ldmx4t(bhf,     a0);
            ldmx4t(bhf + 4, a0 + 32 * 144);
            #pragma unroll
            for (int blk = 0; blk < 2; blk++)
                #pragma unroll
                for (int kk = 0; kk < 4; kk++) {
                    mma16816(s[blk][j], qhi[blk][kk], bhf[2 * kk], bhf[2 * kk + 1]);
                    mma16816(s[blk][j], qlo[blk][kk], bhf[2 * kk], bhf[2 * kk + 1]);
                }
        }

        // ---- online softmax: 4 rows per thread (blk x {g, g+8}) ----
        float f[4];
        #pragma unroll
        for (int blk = 0; blk < 2; blk++) {
            float mx0 = m[2 * blk], mx1 = m[2 * blk + 1];
            #pragma unroll
            for (int j = 0; j < 8; j++) {
                mx0 = fmaxf(mx0, fmaxf(s[blk][j][0], s[blk][j][1]));
                mx1 = fmaxf(mx1, fmaxf(s[blk][j][2], s[blk][j][3]));
            }
            mx0 = fmaxf(mx0, __shfl_xor_sync(0xffffffffu, mx0, 1));
            mx0 = fmaxf(mx0, __shfl_xor_sync(0xffffffffu, mx0, 2));
            mx1 = fmaxf(mx1, __shfl_xor_sync(0xffffffffu, mx1, 1));
            mx1 = fmaxf(mx1, __shfl_xor_sync(0xffffffffu, mx1, 2));
            f[2 * blk]     = __expf(m[2 * blk] - mx0);
            f[2 * blk + 1] = __expf(m[2 * blk + 1] - mx1);
            m[2 * blk] = mx0; m[2 * blk + 1] = mx1;
            float s0 = 0.0f, s1 = 0.0f;
            #pragma unroll
            for (int j = 0; j < 8; j++) {
                s[blk][j][0] = __expf(s[blk][j][0] - mx0); s0 += s[blk][j][0];
                s[blk][j][1] = __expf(s[blk][j][1] - mx0); s0 += s[blk][j][1];
                s[blk][j][2] = __expf(s[blk][j][2] - mx1); s1 += s[blk][j][2];
                s[blk][j][3] = __expf(s[blk][j][3] - mx1); s1 += s[blk][j][3];
            }
            s0 += __shfl_xor_sync(0xffffffffu, s0, 1);
            s0 += __shfl_xor_sync(0xffffffffu, s0, 2);
            s1 += __shfl_xor_sync(0xffffffffu, s1, 1);
            s1 += __shfl_xor_sync(0xffffffffu, s1, 2);
            l[2 * blk]     = l[2 * blk]     * f[2 * blk]     + s0;
            l[2 * blk + 1] = l[2 * blk + 1] * f[2 * blk + 1] + s1;
        }

        // ---- P A-fragments (register pass-through) ----
        uint32_t ap[2][4][4];
        #pragma unroll
        for (int blk = 0; blk < 2; blk++)
            #pragma unroll
            for (int kk = 0; kk < 4; kk++) {
                ap[blk][kk][0] = pack2(s[blk][2 * kk][0],     s[blk][2 * kk][1]);
                ap[blk][kk][1] = pack2(s[blk][2 * kk][2],     s[blk][2 * kk][3]);
                ap[blk][kk][2] = pack2(s[blk][2 * kk + 1][0], s[blk][2 * kk + 1][1]);
                ap[blk][kk][3] = pack2(s[blk][2 * kk + 1][2], s[blk][2 * kk + 1][3]);
            }

        // ---- PV: rescale O, accumulate; V-frags via ldmatrix ----
        #pragma unroll
        for (int jc = 0; jc < 8; jc++) {
            uint32_t vf[8];
            uint32_t va = sb + OFF_VHI + (8 * jc + (lane & 7)) * 144 + (lane >> 3) * 16;
            ldmx4(vf,     va);
            ldmx4(vf + 4, va + 64);
            #pragma unroll
            for (int blk = 0; blk < 2; blk++) {
                o[blk][jc][0] *= f[2 * blk];
                o[blk][jc][1] *= f[2 * blk];
                o[blk][jc][2] *= f[2 * blk + 1];
                o[blk][jc][3] *= f[2 * blk + 1];
                #pragma unroll
                for (int kk = 0; kk < 4; kk++)
                    mma16816(o[blk][jc], ap[blk][kk], vf[2 * kk], vf[2 * kk + 1]);
            }
        }

        // ---- pipeline: stage kt+2, convert kt+1 ----
        if (kt + 2 < NKT) stage_kv(sb, kb, vb, kt + 2, kt & 1, tid);
        __syncthreads();                       // all warps done reading half tiles
        if (kt + 1 < NKT) {
            if (kt + 2 < NKT) cp_wait<1>(); else cp_wait<0>();
            convert_kv(smc, (kt + 1) & 1, tid);
            __syncthreads();
        }
    }

    // ---- epilogue: direct scalar stores (8 lanes fill each 32B sector) ----
    float inv[4];
    #pragma unroll
    for (int r = 0; r < 4; r++) inv[r] = 1.0f / l[r];

    float* ob = out + (size_t)batch * (512 * LEN) + (size_t)(h * 64) * LEN + qt * 256;
    #pragma unroll
    for (int blk = 0; blk < 2; blk++) {
        int ta = warp * 32 + blk * 16 + g;
        #pragma unroll
        for (int jc = 0; jc < 8; jc++) {
            int c = 8 * jc + 2 * tig;
            ob[(size_t)c * LEN + ta]           = o[blk][jc][0] * inv[2 * blk];
            ob[(size_t)(c + 1) * LEN + ta]     = o[blk][jc][1] * inv[2 * blk];
            ob[(size_t)c * LEN + ta + 8]       = o[blk][jc][2] * inv[2 * blk + 1];
            ob[(size_t)(c + 1) * LEN + ta + 8] = o[blk][jc][3] * inv[2 * blk + 1];
        }
    }
}

extern "C" void kernel_launch(void* const* d_in, const int* in_sizes, int n_in,
                              void* d_out, int out_size)
{
    const float* qkv = (const float*)d_in[0];
    float* out = (float*)d_out;

    cudaFuncSetAttribute(attn_hmma3_kernel,
                         cudaFuncAttributeMaxDynamicSharedMemorySize, SMEM_BYTES);

    dim3 grid(LEN / 256, 64);   // 8 q-tiles x 64 head-batches = 512 CTAs
    attn_hmma3_kernel<<<grid, 256, SMEM_BYTES>>>(qkv, out);
}